// round 6
// baseline (speedup 1.0000x reference)
#include <cuda_runtime.h>
#include <cstdint>

// ---------------------------------------------------------------------------
// HeteroGAT — R5 structure (co-launched DAG, batched GATs) with 3xTF32
// tensor-core GEMM bodies replacing the fp32 FFMA GEMMs.
// ---------------------------------------------------------------------------

#define NNODE  16384
#define IN_DIM 128
#define HID    64
#define OUTF   349
#define NEDGE  262144
#define NEG_SLOPE 0.2f

constexpr long long NHF = (long long)NNODE * HID;
constexpr long long N4  = (long long)NNODE * 4;

constexpr long long OFF_FA0   = 0;
constexpr long long OFF_FP0   = OFF_FA0 + NHF;
constexpr long long OFF_FP1   = OFF_FP0 + NHF;
constexpr long long OFF_FP2   = OFF_FP1 + NHF;
constexpr long long OFF_FA2   = OFF_FP2 + NHF;
constexpr long long OFF_F1A   = OFF_FA2 + NHF;
constexpr long long OFF_F1PD  = OFF_F1A + NHF;
constexpr long long OFF_F1PC  = OFF_F1PD + NHF;
constexpr long long OFF_OUTPW = OFF_F1PC + NHF;
constexpr long long OFF_OUTPC = OFF_OUTPW + NHF;
constexpr long long OFF_O1W   = OFF_OUTPC + NHF;
constexpr long long OFF_O1C   = OFF_O1W + NHF;
constexpr long long OFF_HA1   = OFF_O1C + NHF;
constexpr long long OFF_HF    = OFF_HA1 + NHF;
constexpr long long OFF_ELER  = OFF_HF + 2 * NHF;       // 10 x N4
constexpr long long OFF_DEG   = OFF_ELER + 10 * N4;     // ints below
constexpr long long OFF_RP    = OFF_DEG + 3LL * NNODE;
constexpr long long OFF_CSR   = OFF_RP + 3LL * (NNODE + 1);
constexpr long long SCRATCH_TOTAL = OFF_CSR + 3LL * NEDGE + 16;

__device__ float g_scratch[SCRATCH_TOTAL];

__device__ __forceinline__ float leaky(float x) {
    return x > 0.f ? x : NEG_SLOPE * x;
}

// ---------------------------------------------------------------------------
// small kernels
// ---------------------------------------------------------------------------
__global__ void zero_int_kernel(int* __restrict__ p, int n) {
    int i = blockIdx.x * blockDim.x + threadIdx.x;
    if (i < n) p[i] = 0;
}

__global__ __launch_bounds__(1024) void scan3_kernel(int* __restrict__ deg,
                                                     int* __restrict__ rp) {
    __shared__ int sh[1024];
    int t = threadIdx.x;
    int g = blockIdx.x;
    int* dg = deg + g * NNODE;
    int* r  = rp + g * (NNODE + 1);
    int loc[16];
    int run = 0;
    int base = t * 16;
#pragma unroll
    for (int i = 0; i < 16; i++) { loc[i] = run; run += dg[base + i]; }
    sh[t] = run;
    __syncthreads();
    for (int d = 1; d < 1024; d <<= 1) {
        int v = sh[t];
        int a = (t >= d) ? sh[t - d] : 0;
        __syncthreads();
        sh[t] = v + a;
        __syncthreads();
    }
    int off = (t == 0) ? 0 : sh[t - 1];
#pragma unroll
    for (int i = 0; i < 16; i++) {
        int v = off + loc[i];
        r[base + i] = v;
        dg[base + i] = v;
    }
    if (t == 1023) r[NNODE] = off + run;
}

// ---------------------------------------------------------------------------
// TF32 helpers (R4-proven)
// ---------------------------------------------------------------------------
__device__ __forceinline__ void split_tf32(float v, float& hi, float& lo) {
    uint32_t hb; asm("cvt.rna.tf32.f32 %0, %1;" : "=r"(hb) : "f"(v));
    hi = __uint_as_float(hb);
    float l = v - hi;
    uint32_t lb; asm("cvt.rna.tf32.f32 %0, %1;" : "=r"(lb) : "f"(l));
    lo = __uint_as_float(lb);
}

#define MMA_TF32(d, a0, a1, a2, a3, b0, b1)                                      \
    asm volatile("mma.sync.aligned.m16n8k8.row.col.f32.tf32.tf32.f32 "           \
                 "{%0,%1,%2,%3}, {%4,%5,%6,%7}, {%8,%9}, {%0,%1,%2,%3};"         \
                 : "+f"((d).x), "+f"((d).y), "+f"((d).z), "+f"((d).w)            \
                 : "r"(__float_as_uint(a0)), "r"(__float_as_uint(a1)),           \
                   "r"(__float_as_uint(a2)), "r"(__float_as_uint(a3)),           \
                   "r"(__float_as_uint(b0)), "r"(__float_as_uint(b1)))

// ---------------------------------------------------------------------------
// 3xTF32 GEMM body: C[.,64] tile of 128 rows; optional fused A-prep
// (scale / add-A2 / col-bias x2 / relu) applied before the hi/lo split.
// Block 128x64, 8 warps (warp tile 32x32), BK=16.
// ---------------------------------------------------------------------------
struct GJob {
    const float* A;
    const float* A2;
    const float* scale;
    const float* ab0;
    const float* ab1;
    int relu;
    const float* W;
    float* C;
};
struct GBatch { GJob j[5]; int K; };

__device__ __forceinline__ void gemm_tf32_body(const GJob jb, int K, int tile, int tid) {
    __shared__ float Ah[128][20], Al[128][20];   // lanes hit all 32 banks
    __shared__ float Wh[16][72], Wl[16][72];
    int wid = tid >> 5, lane = tid & 31;
    int warpM = wid & 3, warpN = wid >> 2;
    int g = lane >> 2, t4 = lane & 3;
    int row0 = tile * 128;
    float4 acc[2][4] = {};

    for (int kt = 0; kt < K; kt += 16) {
#pragma unroll
        for (int i = 0; i < 8; i++) {            // A: 128x16
            int idx = tid + i * 256;
            int r = idx >> 4, k = idx & 15;
            int kc = kt + k;
            long long off = (long long)(row0 + r) * K + kc;
            float v = jb.A[off];
            if (jb.scale) v *= jb.scale[kc];
            if (jb.A2)    v += jb.A2[off];
            if (jb.ab0)   v += jb.ab0[kc];
            if (jb.ab1)   v += jb.ab1[kc];
            if (jb.relu)  v = fmaxf(v, 0.f);
            float hi, lo; split_tf32(v, hi, lo);
            Ah[r][k] = hi; Al[r][k] = lo;
        }
#pragma unroll
        for (int i = 0; i < 4; i++) {            // W: 16x64
            int idx = tid + i * 256;
            int k = idx >> 6, c = idx & 63;
            float v = jb.W[(long long)(kt + k) * 64 + c];
            float hi, lo; split_tf32(v, hi, lo);
            Wh[k][c] = hi; Wl[k][c] = lo;
        }
        __syncthreads();
#pragma unroll
        for (int kk = 0; kk < 2; kk++) {
            int k8 = kk * 8;
            float bh[4][2], bl[4][2];
#pragma unroll
            for (int ni = 0; ni < 4; ni++) {
                int n = warpN * 32 + ni * 8 + g;
                bh[ni][0] = Wh[k8 + t4][n];     bh[ni][1] = Wh[k8 + t4 + 4][n];
                bl[ni][0] = Wl[k8 + t4][n];     bl[ni][1] = Wl[k8 + t4 + 4][n];
            }
#pragma unroll
            for (int mi = 0; mi < 2; mi++) {
                int r = warpM * 32 + mi * 16;
                float ah0 = Ah[r + g][k8 + t4],     ah1 = Ah[r + g + 8][k8 + t4];
                float ah2 = Ah[r + g][k8 + t4 + 4], ah3 = Ah[r + g + 8][k8 + t4 + 4];
                float al0 = Al[r + g][k8 + t4],     al1 = Al[r + g + 8][k8 + t4];
                float al2 = Al[r + g][k8 + t4 + 4], al3 = Al[r + g + 8][k8 + t4 + 4];
#pragma unroll
                for (int ni = 0; ni < 4; ni++) {
                    MMA_TF32(acc[mi][ni], ah0, ah1, ah2, ah3, bh[ni][0], bh[ni][1]);
                    MMA_TF32(acc[mi][ni], ah0, ah1, ah2, ah3, bl[ni][0], bl[ni][1]);
                    MMA_TF32(acc[mi][ni], al0, al1, al2, al3, bh[ni][0], bh[ni][1]);
                }
            }
        }
        __syncthreads();
    }
#pragma unroll
    for (int mi = 0; mi < 2; mi++) {
        long long rb = row0 + warpM * 32 + mi * 16 + g;
#pragma unroll
        for (int ni = 0; ni < 4; ni++) {
            int c = warpN * 32 + ni * 8 + 2 * t4;
            float4 v = acc[mi][ni];
            *(float2*)&jb.C[rb * 64 + c] = make_float2(v.x, v.y);
            *(float2*)&jb.C[(rb + 8) * 64 + c] = make_float2(v.z, v.w);
        }
    }
}

__global__ __launch_bounds__(256) void gemm_tf32_kernel(GBatch p) {
    gemm_tf32_body(p.j[blockIdx.y], p.K, blockIdx.x, threadIdx.x);
}

// ---- full 3xTF32 GEMM with bias + arbitrary Ncols (final projection) ----
__global__ __launch_bounds__(256) void gemm_tf32_full_kernel(
    const float* __restrict__ A, const float* __restrict__ W,
    const float* __restrict__ bias, float* __restrict__ C,
    int K, int Ncols) {
    __shared__ float Ah[128][20], Al[128][20];
    __shared__ float Wh[16][72], Wl[16][72];
    int tid = threadIdx.x;
    int wid = tid >> 5, lane = tid & 31;
    int warpM = wid & 3, warpN = wid >> 2;
    int g = lane >> 2, t4 = lane & 3;
    int row0 = blockIdx.x * 128;
    int col0 = blockIdx.y * 64;
    float4 acc[2][4] = {};

    for (int kt = 0; kt < K; kt += 16) {
#pragma unroll
        for (int i = 0; i < 8; i++) {
            int idx = tid + i * 256;
            int r = idx >> 4, k = idx & 15;
            float v = A[(long long)(row0 + r) * K + kt + k];
            float hi, lo; split_tf32(v, hi, lo);
            Ah[r][k] = hi; Al[r][k] = lo;
        }
#pragma unroll
        for (int i = 0; i < 4; i++) {
            int idx = tid + i * 256;
            int k = idx >> 6, c = idx & 63;
            int gc = col0 + c;
            float v = (gc < Ncols) ? W[(long long)(kt + k) * Ncols + gc] : 0.0f;
            float hi, lo; split_tf32(v, hi, lo);
            Wh[k][c] = hi; Wl[k][c] = lo;
        }
        __syncthreads();
#pragma unroll
        for (int kk = 0; kk < 2; kk++) {
            int k8 = kk * 8;
            float bh[4][2], bl[4][2];
#pragma unroll
            for (int ni = 0; ni < 4; ni++) {
                int n = warpN * 32 + ni * 8 + g;
                bh[ni][0] = Wh[k8 + t4][n];     bh[ni][1] = Wh[k8 + t4 + 4][n];
                bl[ni][0] = Wl[k8 + t4][n];     bl[ni][1] = Wl[k8 + t4 + 4][n];
            }
#pragma unroll
            for (int mi = 0; mi < 2; mi++) {
                int r = warpM * 32 + mi * 16;
                float ah0 = Ah[r + g][k8 + t4],     ah1 = Ah[r + g + 8][k8 + t4];
                float ah2 = Ah[r + g][k8 + t4 + 4], ah3 = Ah[r + g + 8][k8 + t4 + 4];
                float al0 = Al[r + g][k8 + t4],     al1 = Al[r + g + 8][k8 + t4];
                float al2 = Al[r + g][k8 + t4 + 4], al3 = Al[r + g + 8][k8 + t4 + 4];
#pragma unroll
                for (int ni = 0; ni < 4; ni++) {
                    MMA_TF32(acc[mi][ni], ah0, ah1, ah2, ah3, bh[ni][0], bh[ni][1]);
                    MMA_TF32(acc[mi][ni], ah0, ah1, ah2, ah3, bl[ni][0], bl[ni][1]);
                    MMA_TF32(acc[mi][ni], al0, al1, al2, al3, bh[ni][0], bh[ni][1]);
                }
            }
        }
        __syncthreads();
    }
#pragma unroll
    for (int mi = 0; mi < 2; mi++) {
        long long rb = row0 + warpM * 32 + mi * 16 + g;
#pragma unroll
        for (int ni = 0; ni < 4; ni++) {
            int c = col0 + warpN * 32 + ni * 8 + 2 * t4;
            float4 v = acc[mi][ni];
            if (c < Ncols) {
                C[rb * Ncols + c] = v.x + bias[c];
                C[(rb + 8) * Ncols + c] = v.z + bias[c];
            }
            if (c + 1 < Ncols) {
                C[rb * Ncols + c + 1] = v.y + bias[c + 1];
                C[(rb + 8) * Ncols + c + 1] = v.w + bias[c + 1];
            }
        }
    }
}

// ---------------------------------------------------------------------------
// eler body (R2-proven)
// ---------------------------------------------------------------------------
struct EJob { const float* F; const float* a; float* out; };
struct E6 { EJob j[6]; };

__device__ __forceinline__ void eler_body(const EJob p, int i) {
    int node = i >> 2, h = i & 3;
    const float4* f = (const float4*)(p.F + (long long)node * HID + h * 16);
    const float4* a = (const float4*)(p.a + h * 16);
    float s = 0.f;
#pragma unroll
    for (int j = 0; j < 4; j++) {
        float4 fv = f[j], av = a[j];
        s += fv.x * av.x + fv.y * av.y + fv.z * av.z + fv.w * av.w;
    }
    p.out[i] = s;
}

__global__ void eler_kernel(E6 p) {
    eler_body(p.j[blockIdx.y], blockIdx.x * blockDim.x + threadIdx.x);
}

// ---------------------------------------------------------------------------
// combined launches: hist + 5 tf32 GEMMs, scatter + 6 eler jobs
// ---------------------------------------------------------------------------
__global__ __launch_bounds__(256) void hist_gemm_kernel(
    const int* __restrict__ d0, const int* __restrict__ d1, const int* __restrict__ d2,
    int* __restrict__ deg, GBatch p) {
    if (blockIdx.x < 3072) {
        int t = blockIdx.x * 256 + threadIdx.x;     // < 3*NEDGE exactly
        int g = t >> 18;
        int e = t & (NEDGE - 1);
        const int* ds = (g == 0) ? d0 : (g == 1) ? d1 : d2;
        atomicAdd(&deg[g * NNODE + ds[e]], 1);
    } else {
        int b = blockIdx.x - 3072;
        gemm_tf32_body(p.j[b >> 7], p.K, b & 127, threadIdx.x);
    }
}

__global__ __launch_bounds__(256) void scatter_eler_kernel(
    const int* __restrict__ s0, const int* __restrict__ d0,
    const int* __restrict__ s1, const int* __restrict__ d1,
    const int* __restrict__ s2, const int* __restrict__ d2,
    int* __restrict__ cur, int* __restrict__ csr, E6 p) {
    if (blockIdx.x < 3072) {
        int t = blockIdx.x * 256 + threadIdx.x;
        int g = t >> 18;
        int e = t & (NEDGE - 1);
        const int* ss = (g == 0) ? s0 : (g == 1) ? s1 : s2;
        const int* ds = (g == 0) ? d0 : (g == 1) ? d1 : d2;
        int d = ds[e];
        int pos = atomicAdd(&cur[g * NNODE + d], 1);
        csr[(long long)g * NEDGE + pos] = ss[e];
    } else {
        int b = blockIdx.x - 3072;
        eler_body(p.j[b >> 8], (b & 255) * 256 + threadIdx.x);
    }
}

// ---------------------------------------------------------------------------
// Fused GAT (R2-proven, 1 warp/node), batched over independent jobs
// ---------------------------------------------------------------------------
struct GatJob {
    const int* rp; const int* csr;
    const float* el; const float* er; const float* fs;
    const float* ba; int relu;
    float* out;
};
struct GatB { GatJob j[3]; };

#define MERGE(m, s)                                                        \
    {                                                                      \
        float om = __shfl_xor_sync(0xFFFFFFFFu, (m), off);                 \
        float os = __shfl_xor_sync(0xFFFFFFFFu, (s), off);                 \
        float nm = fmaxf((m), om);                                         \
        (s) = (s) * __expf((m) - nm) + os * __expf(om - nm);               \
        (m) = nm;                                                          \
    }

__global__ __launch_bounds__(256) void gat_kernel(GatB p) {
    GatJob jb = p.j[blockIdx.y];
    int w = (blockIdx.x * blockDim.x + threadIdx.x) >> 5;
    int lane = threadIdx.x & 31;
    if (w >= NNODE) return;
    int d = w;
    int beg = jb.rp[d], end = jb.rp[d + 1];
    float4 er4 = *(const float4*)(jb.er + 4 * d);

    float m0 = -1e30f, m1 = -1e30f, m2 = -1e30f, m3 = -1e30f;
    float s0 = 0.f, s1 = 0.f, s2 = 0.f, s3 = 0.f;
    for (int i = beg + lane; i < end; i += 32) {
        int s = jb.csr[i];
        float4 l4 = *(const float4*)(jb.el + 4 * s);
        float e0 = leaky(l4.x + er4.x);
        float e1 = leaky(l4.y + er4.y);
        float e2 = leaky(l4.z + er4.z);
        float e3 = leaky(l4.w + er4.w);
        float nm;
        nm = fmaxf(m0, e0); s0 = s0 * __expf(m0 - nm) + __expf(e0 - nm); m0 = nm;
        nm = fmaxf(m1, e1); s1 = s1 * __expf(m1 - nm) + __expf(e1 - nm); m1 = nm;
        nm = fmaxf(m2, e2); s2 = s2 * __expf(m2 - nm) + __expf(e2 - nm); m2 = nm;
        nm = fmaxf(m3, e3); s3 = s3 * __expf(m3 - nm) + __expf(e3 - nm); m3 = nm;
    }
#pragma unroll
    for (int off = 16; off; off >>= 1) {
        MERGE(m0, s0) MERGE(m1, s1) MERGE(m2, s2) MERGE(m3, s3)
    }
    float inv0 = 1.f / fmaxf(s0, 1e-9f);
    float inv1 = 1.f / fmaxf(s1, 1e-9f);
    float inv2 = 1.f / fmaxf(s2, 1e-9f);
    float inv3 = 1.f / fmaxf(s3, 1e-9f);

    bool hi = (lane & 16) != 0;
    float mA = hi ? m1 : m0, iA = hi ? inv1 : inv0, eA = hi ? er4.y : er4.x;
    float mB = hi ? m3 : m2, iB = hi ? inv3 : inv2, eB = hi ? er4.w : er4.z;
    float acc0 = 0.f, acc1 = 0.f;
    for (int i = beg; i < end; i++) {
        int s = jb.csr[i];
        float4 l4 = *(const float4*)(jb.el + 4 * s);
        float lA = hi ? l4.y : l4.x;
        float lB = hi ? l4.w : l4.z;
        float w0 = __expf(leaky(lA + eA) - mA) * iA;
        float w1 = __expf(leaky(lB + eB) - mB) * iB;
        const float* fr = jb.fs + (long long)s * HID;
        acc0 += fr[lane] * w0;
        acc1 += fr[lane + 32] * w1;
    }
    long long ob = (long long)d * HID;
    if (jb.ba) { acc0 += jb.ba[lane]; acc1 += jb.ba[lane + 32]; }
    if (jb.relu) { acc0 = fmaxf(acc0, 0.f); acc1 = fmaxf(acc1, 0.f); }
    jb.out[ob + lane] = acc0;
    jb.out[ob + lane + 32] = acc1;
}

// ---------------------------------------------------------------------------
// hf: sums the two layer-1 GAT partials, adds biases + scalar C (inline —
// _ln over the size-1 feature axis equals its bias exactly), then writes
// [l2norm(h1), l2norm(h1+C)].
// ---------------------------------------------------------------------------
__global__ __launch_bounds__(256) void hf_kernel(
    const float* __restrict__ accW, const float* __restrict__ accC,
    const float* __restrict__ b1,
    const float* __restrict__ ln1_gb, const float* __restrict__ attn_w,
    const float* __restrict__ attn_b, const float* __restrict__ ln2_gb,
    const float* __restrict__ ffn_w1, const float* __restrict__ ffn_b1,
    const float* __restrict__ ffn_w2, const float* __restrict__ ffn_b2,
    float* __restrict__ hf) {
    __shared__ float sC;
    if (threadIdx.x == 0) {
        float y1 = ln1_gb[1];
        float v = y1 * attn_w[2] + attn_b[2];
        float o = v * attn_w[3] + attn_b[3];
        float y2 = ln2_gb[1];
        float f = ffn_b2[0];
        for (int j = 0; j < 16; j++) {
            float z = y2 * ffn_w1[j] + ffn_b1[j];
            float g = 0.5f * z * (1.0f + erff(z * 0.70710678118654752f));
            f += g * ffn_w2[j];
        }
        sC = o + f;
    }
    __syncthreads();
    float C = sC;

    int g = blockIdx.x * blockDim.x + threadIdx.x;
    int row = g >> 5;
    int lane = g & 31;
    if (row >= NNODE) return;
    long long base = (long long)row * HID;
    float v0 = accW[base + lane]      + accC[base + lane]
             + b1[lane]      + b1[64 + lane];
    float v1 = accW[base + lane + 32] + accC[base + lane + 32]
             + b1[lane + 32] + b1[96 + lane];
    float w0 = v0 + C, w1 = v1 + C;
    float s1 = v0 * v0 + v1 * v1;
    float s2 = w0 * w0 + w1 * w1;
#pragma unroll
    for (int o = 16; o; o >>= 1) {
        s1 += __shfl_xor_sync(0xFFFFFFFFu, s1, o);
        s2 += __shfl_xor_sync(0xFFFFFFFFu, s2, o);
    }
    float i1 = 1.f / fmaxf(sqrtf(s1), 1e-12f);
    float i2 = 1.f / fmaxf(sqrtf(s2), 1e-12f);
    long long hb = (long long)row * 128;
    hf[hb + lane]       = v0 * i1;
    hf[hb + lane + 32]  = v1 * i1;
    hf[hb + 64 + lane]  = w0 * i2;
    hf[hb + 96 + lane]  = w1 * i2;
}

// ---------------------------------------------------------------------------
extern "C" void kernel_launch(void* const* d_in, const int* in_sizes, int n_in,
                              void* d_out, int out_size) {
    const float* x_author = (const float*)d_in[0];
    const float* x_paper  = (const float*)d_in[1];
    const float* ntype    = (const float*)d_in[2];
    const float* W0       = (const float*)d_in[3];
    const float* al0      = (const float*)d_in[4];
    const float* ar0      = (const float*)d_in[5];
    const float* b0       = (const float*)d_in[6];
    const float* W1       = (const float*)d_in[7];
    const float* al1      = (const float*)d_in[8];
    const float* ar1      = (const float*)d_in[9];
    const float* b1       = (const float*)d_in[10];
    const float* ln1_gb   = (const float*)d_in[11];
    const float* attn_w   = (const float*)d_in[12];
    const float* attn_b   = (const float*)d_in[13];
    const float* ln2_gb   = (const float*)d_in[14];
    const float* ffn_w1   = (const float*)d_in[15];
    const float* ffn_b1   = (const float*)d_in[16];
    const float* ffn_w2   = (const float*)d_in[17];
    const float* ffn_b2   = (const float*)d_in[18];
    const float* lin_W    = (const float*)d_in[19];
    const float* lin_b    = (const float*)d_in[20];
    const int* src_w = (const int*)d_in[21];
    const int* dst_w = (const int*)d_in[22];
    const int* src_c = (const int*)d_in[23];
    const int* dst_c = (const int*)d_in[24];
    const int* src_r = (const int*)d_in[25];
    const int* dst_r = (const int*)d_in[26];
    float* out = (float*)d_out;

    float* S = nullptr;
    cudaGetSymbolAddress((void**)&S, g_scratch);

    float* Fa0   = S + OFF_FA0;
    float* Fp0   = S + OFF_FP0;
    float* Fp1   = S + OFF_FP1;
    float* Fp2   = S + OFF_FP2;
    float* Fa2   = S + OFF_FA2;
    float* F1a   = S + OFF_F1A;
    float* F1pd  = S + OFF_F1PD;
    float* F1pc  = S + OFF_F1PC;
    float* outpW = S + OFF_OUTPW;
    float* outpC = S + OFF_OUTPC;
    float* o1w   = S + OFF_O1W;
    float* o1c   = S + OFF_O1C;
    float* ha1   = S + OFF_HA1;
    float* hf    = S + OFF_HF;
    float* el_w  = S + OFF_ELER + 0 * N4;
    float* er_w  = S + OFF_ELER + 1 * N4;
    float* el_c  = S + OFF_ELER + 2 * N4;
    float* er_c  = S + OFF_ELER + 3 * N4;
    float* el_r  = S + OFF_ELER + 4 * N4;
    float* er_r  = S + OFF_ELER + 5 * N4;
    float* el1w  = S + OFF_ELER + 6 * N4;
    float* er1w  = S + OFF_ELER + 7 * N4;
    float* el1c  = S + OFF_ELER + 8 * N4;
    float* er1c  = S + OFF_ELER + 9 * N4;
    int* degB = (int*)(S + OFF_DEG);
    int* rpB  = (int*)(S + OFF_RP);
    int* csrB = (int*)(S + OFF_CSR);

    const int* rp_w = rpB + 0 * (NNODE + 1);
    const int* rp_c = rpB + 1 * (NNODE + 1);
    const int* rp_r = rpB + 2 * (NNODE + 1);
    const int* csr_w = csrB + 0LL * NEDGE;
    const int* csr_c = csrB + 1LL * NEDGE;
    const int* csr_r = csrB + 2LL * NEDGE;

    const float* nt0 = ntype;
    const float* nt1 = ntype + IN_DIM;

    // L1: zero CSR counters
    zero_int_kernel<<<192, 256>>>(degB, 3 * NNODE);

    // L2: hist (CSR) + 5 layer-0 tf32 GEMMs (128-row tiles), co-launched
    GBatch g0;
    g0.j[0] = { x_author, nullptr, nt0, nullptr, nullptr, 0, W0 + 0 * 8192, Fa0 };
    g0.j[1] = { x_paper,  nullptr, nt1, nullptr, nullptr, 0, W0 + 0 * 8192, Fp0 };
    g0.j[2] = { x_paper,  nullptr, nt1, nullptr, nullptr, 0, W0 + 1 * 8192, Fp1 };
    g0.j[3] = { x_paper,  nullptr, nt1, nullptr, nullptr, 0, W0 + 2 * 8192, Fp2 };
    g0.j[4] = { x_author, nullptr, nt0, nullptr, nullptr, 0, W0 + 2 * 8192, Fa2 };
    g0.K = IN_DIM;
    hist_gemm_kernel<<<3072 + 5 * 128, 256>>>(dst_w, dst_c, dst_r, degB, g0);

    // L3: scan (row_ptr + cursors)
    scan3_kernel<<<3, 1024>>>(degB, rpB);

    // L4: scatter (CSR fill) + 6 layer-0 eler jobs, co-launched
    E6 e0;
    e0.j[0] = { Fa0, al0 + 0 * 64, el_w };
    e0.j[1] = { Fp0, ar0 + 0 * 64, er_w };
    e0.j[2] = { Fp1, al0 + 1 * 64, el_c };
    e0.j[3] = { Fp1, ar0 + 1 * 64, er_c };
    e0.j[4] = { Fp2, al0 + 2 * 64, el_r };
    e0.j[5] = { Fa2, ar0 + 2 * 64, er_r };
    scatter_eler_kernel<<<3072 + 6 * 256, 256>>>(src_w, dst_w, src_c, dst_c,
                                                 src_r, dst_r, degB, csrB, e0);

    // L5: all three layer-0 GATs batched
    GatB ga;
    ga.j[0] = { rp_w, csr_w, el_w, er_w, Fa0, nullptr,  0, outpW };
    ga.j[1] = { rp_c, csr_c, el_c, er_c, Fp1, nullptr,  0, outpC };
    ga.j[2] = { rp_r, csr_r, el_r, er_r, Fp2, b0 + 128, 1, ha1 };
    gat_kernel<<<dim3(2048, 3), 256>>>(ga);

    // L6: 3 layer-1 tf32 GEMMs; hp1 = relu(outpW+outpC+b0[0]+b0[1]) fused in A-load
    GBatch g1;
    g1.j[0] = { ha1,   nullptr, nullptr, nullptr, nullptr,  0, W1 + 0 * 4096, F1a };
    g1.j[1] = { outpW, outpC,   nullptr, b0,      b0 + 64,  1, W1 + 0 * 4096, F1pd };
    g1.j[2] = { outpW, outpC,   nullptr, b0,      b0 + 64,  1, W1 + 1 * 4096, F1pc };
    g1.j[3] = g1.j[4] = { nullptr, nullptr, nullptr, nullptr, nullptr, 0, nullptr, nullptr };
    g1.K = HID;
    gemm_tf32_kernel<<<dim3(128, 3), 256>>>(g1);

    // L7: 4 layer-1 eler jobs
    E6 e1;
    e1.j[0] = { F1a,  al1 + 0 * 64, el1w };
    e1.j[1] = { F1pd, ar1 + 0 * 64, er1w };
    e1.j[2] = { F1pc, al1 + 1 * 64, el1c };
    e1.j[3] = { F1pc, ar1 + 1 * 64, er1c };
    e1.j[4] = e1.j[5] = { nullptr, nullptr, nullptr };
    eler_kernel<<<dim3(256, 4), 256>>>(e1);

    // L8: both layer-1 GATs batched (separate partials)
    GatB gc;
    gc.j[0] = { rp_w, csr_w, el1w, er1w, F1a,  nullptr, 0, o1w };
    gc.j[1] = { rp_c, csr_c, el1c, er1c, F1pc, nullptr, 0, o1c };
    gc.j[2] = { nullptr, nullptr, nullptr, nullptr, nullptr, nullptr, 0, nullptr };
    gat_kernel<<<dim3(2048, 2), 256>>>(gc);

    // L9: hf (sums partials, inline scalar C, l2-normalized concat)
    hf_kernel<<<2048, 256>>>(o1w, o1c, b1, ln1_gb, attn_w, attn_b, ln2_gb,
                             ffn_w1, ffn_b1, ffn_w2, ffn_b2, hf);

    // L10: final projection (3xTF32)
    gemm_tf32_full_kernel<<<dim3(128, 6), 256>>>(hf, lin_W, lin_b, out, 2 * HID, OUTF);
}

// round 7
// speedup vs baseline: 1.0509x; 1.0509x over previous
#include <cuda_runtime.h>
#include <cstdint>

// ---------------------------------------------------------------------------
// HeteroGAT — R5 DAG + FFMA2 (f32x2) GEMMs + Wal logit refactor
// ---------------------------------------------------------------------------

#define NNODE  16384
#define IN_DIM 128
#define HID    64
#define OUTF   349
#define NEDGE  262144
#define NEG_SLOPE 0.2f

constexpr long long NHF = (long long)NNODE * HID;

constexpr long long OFF_FA0   = 0;
constexpr long long OFF_FP1   = OFF_FA0 + NHF;
constexpr long long OFF_FP2   = OFF_FP1 + NHF;
constexpr long long OFF_F1A   = OFF_FP2 + NHF;
constexpr long long OFF_F1PC  = OFF_F1A + NHF;
constexpr long long OFF_OUTPW = OFF_F1PC + NHF;
constexpr long long OFF_OUTPC = OFF_OUTPW + NHF;
constexpr long long OFF_O1W   = OFF_OUTPC + NHF;
constexpr long long OFF_O1C   = OFF_O1W + NHF;
constexpr long long OFF_HA1   = OFF_O1C + NHF;
constexpr long long OFF_HF    = OFF_HA1 + NHF;
constexpr long long OFF_LA    = OFF_HF + 2 * NHF;        // [N][16] logits author L0
constexpr long long OFF_LP    = OFF_LA + 16LL * NNODE;   // paper L0
constexpr long long OFF_L1A   = OFF_LP + 16LL * NNODE;   // ha1 L1
constexpr long long OFF_L1P   = OFF_L1A + 16LL * NNODE;  // hp1 L1
constexpr long long OFF_WAL   = OFF_L1P + 16LL * NNODE;  // 6144 floats
constexpr long long OFF_DEG   = OFF_WAL + 6144;
constexpr long long OFF_RP    = OFF_DEG + 3LL * NNODE;
constexpr long long OFF_CSR   = OFF_RP + 3LL * (NNODE + 1);
constexpr long long SCRATCH_TOTAL = OFF_CSR + 3LL * NEDGE + 16;

__device__ float g_scratch[SCRATCH_TOTAL];

__device__ __forceinline__ float leaky(float x) {
    return x > 0.f ? x : NEG_SLOPE * x;
}

// ---- f32x2 helpers ----
__device__ __forceinline__ unsigned long long pack2(float lo, float hi) {
    unsigned long long r;
    asm("mov.b64 %0, {%1, %2};" : "=l"(r) : "f"(lo), "f"(hi));
    return r;
}
__device__ __forceinline__ unsigned long long dup2(float v) {
    unsigned long long r;
    asm("mov.b64 %0, {%1, %1};" : "=l"(r) : "f"(v));
    return r;
}
__device__ __forceinline__ void unpack2(unsigned long long p, float& lo, float& hi) {
    asm("mov.b64 {%0, %1}, %2;" : "=f"(lo), "=f"(hi) : "l"(p));
}
__device__ __forceinline__ unsigned long long fma2(unsigned long long a,
                                                   unsigned long long b,
                                                   unsigned long long c) {
    unsigned long long d;
    asm("fma.rn.f32x2 %0, %1, %2, %3;" : "=l"(d) : "l"(a), "l"(b), "l"(c));
    return d;
}

// ---------------------------------------------------------------------------
// small kernels: zero + Wal precompute (folds W·a (+ntype) into K x 4 cols)
// ---------------------------------------------------------------------------
__global__ __launch_bounds__(256) void misc_kernel(
    int* __restrict__ deg,
    const float* __restrict__ W0, const float* __restrict__ W1,
    const float* __restrict__ al0, const float* __restrict__ ar0,
    const float* __restrict__ al1, const float* __restrict__ ar1,
    const float* __restrict__ ntype, float* __restrict__ wal) {
    int b = blockIdx.x;
    if (b < 192) {
        deg[b * 256 + threadIdx.x] = 0;
        return;
    }
    int id = (b - 192) * 256 + threadIdx.x;   // 0..6143
    int t, e, base;
    if (id < 2048)      { t = 0; e = id;        base = 0; }
    else if (id < 4096) { t = 1; e = id - 2048; base = 2048; }
    else if (id < 5120) { t = 2; e = id - 4096; base = 4096; }
    else                { t = 3; e = id - 5120; base = 5120; }
    int k = e >> 4, c = e & 15, s = c >> 2, h = c & 3;
    const float* Wm = nullptr;
    const float* av = nullptr;
    const float* sc = nullptr;
    if (t == 0) {
        sc = ntype;
        if (s == 0)      { Wm = W0;             av = al0; }
        else if (s == 1) { Wm = W0 + 2 * 8192;  av = ar0 + 128; }
    } else if (t == 1) {
        sc = ntype + IN_DIM;
        if (s == 0)      { Wm = W0;             av = ar0; }
        else if (s == 1) { Wm = W0 + 8192;      av = al0 + 64; }
        else if (s == 2) { Wm = W0 + 8192;      av = ar0 + 64; }
        else             { Wm = W0 + 2 * 8192;  av = al0 + 128; }
    } else if (t == 2) {
        if (s == 0)      { Wm = W1;             av = al1; }
    } else {
        if (s == 0)      { Wm = W1;             av = ar1; }
        else if (s == 1) { Wm = W1 + 4096;      av = al1 + 64; }
        else if (s == 2) { Wm = W1 + 4096;      av = ar1 + 64; }
    }
    float v = 0.f;
    if (Wm) {
        const float* Wr = Wm + (long long)k * 64 + h * 16;
        const float* ar = av + h * 16;
        float sum = 0.f;
#pragma unroll
        for (int d = 0; d < 16; d++) sum += Wr[d] * ar[d];
        v = sum * (sc ? sc[k] : 1.0f);
    }
    wal[base + k * 16 + c] = v;
}

__global__ __launch_bounds__(1024) void scan3_kernel(int* __restrict__ deg,
                                                     int* __restrict__ rp) {
    __shared__ int sh[1024];
    int t = threadIdx.x;
    int g = blockIdx.x;
    int* dg = deg + g * NNODE;
    int* r  = rp + g * (NNODE + 1);
    int loc[16];
    int run = 0;
    int base = t * 16;
#pragma unroll
    for (int i = 0; i < 16; i++) { loc[i] = run; run += dg[base + i]; }
    sh[t] = run;
    __syncthreads();
    for (int d = 1; d < 1024; d <<= 1) {
        int v = sh[t];
        int a = (t >= d) ? sh[t - d] : 0;
        __syncthreads();
        sh[t] = v + a;
        __syncthreads();
    }
    int off = (t == 0) ? 0 : sh[t - 1];
#pragma unroll
    for (int i = 0; i < 16; i++) {
        int v = off + loc[i];
        r[base + i] = v;
        dg[base + i] = v;
    }
    if (t == 1023) r[NNODE] = off + run;
}

__global__ void scatter_kernel(const int* __restrict__ s0, const int* __restrict__ d0,
                               const int* __restrict__ s1, const int* __restrict__ d1,
                               const int* __restrict__ s2, const int* __restrict__ d2,
                               int* __restrict__ cur, int* __restrict__ csr) {
    int t = blockIdx.x * 256 + threadIdx.x;
    int g = t >> 18;
    int e = t & (NEDGE - 1);
    const int* ss = (g == 0) ? s0 : (g == 1) ? s1 : s2;
    const int* ds = (g == 0) ? d0 : (g == 1) ? d1 : d2;
    int d = ds[e];
    int pos = atomicAdd(&cur[g * NNODE + d], 1);
    csr[(long long)g * NEDGE + pos] = ss[e];
}

// ---------------------------------------------------------------------------
// A-prep (shared by feature + logit GEMMs)
// ---------------------------------------------------------------------------
struct GJob {
    const float* A;
    const float* A2;
    const float* scale;
    const float* ab0;
    const float* ab1;
    int relu;
    const float* W;     // feature: [K][64]; logit: Wcat [K][16]
    float* C;
};

__device__ __forceinline__ float a_prep(const GJob& jb, long long off, int kc) {
    float v = jb.A[off];
    if (jb.scale) v *= jb.scale[kc];
    if (jb.A2)    v += jb.A2[off];
    if (jb.ab0)   v += jb.ab0[kc];
    if (jb.ab1)   v += jb.ab1[kc];
    if (jb.relu)  v = fmaxf(v, 0.f);
    return v;
}

// ---------------------------------------------------------------------------
// Feature GEMM body: 64x64 tile, 4x4 micro, BK=32, FFMA2 inner loop.
// As stored duplicated (a,a) in u64; smem = 32*65*8 + 32*64*4 = 24.8 KB.
// ---------------------------------------------------------------------------
__device__ __forceinline__ void feat_body(const GJob jb, int K, int tile, int tid,
                                          char* sm) {
    unsigned long long* As2 = (unsigned long long*)sm;          // [32][65]
    float* Ws = (float*)(sm + 32 * 65 * 8);                     // [32][64]
    int row0 = tile * 64;
    int tr = (tid >> 4) * 4;
    int tc = (tid & 15) * 4;
    unsigned long long acc[4][2] = {};
    for (int kt = 0; kt < K; kt += 32) {
#pragma unroll
        for (int i = 0; i < 8; i++) {
            int idx = tid + i * 256;
            int r = idx >> 5, k = idx & 31;
            int kc = kt + k;
            float v = a_prep(jb, (long long)(row0 + r) * K + kc, kc);
            As2[k * 65 + r] = dup2(v);
        }
#pragma unroll
        for (int i = 0; i < 8; i++) {
            int idx = tid + i * 256;
            int k = idx >> 6, c = idx & 63;
            Ws[k * 64 + c] = jb.W[(long long)(kt + k) * 64 + c];
        }
        __syncthreads();
#pragma unroll
        for (int k = 0; k < 32; k++) {
            float4 w = *(const float4*)&Ws[k * 64 + tc];
            unsigned long long wab = pack2(w.x, w.y);
            unsigned long long wcd = pack2(w.z, w.w);
            unsigned long long a0 = As2[k * 65 + tr];
            unsigned long long a1 = As2[k * 65 + tr + 1];
            unsigned long long a2 = As2[k * 65 + tr + 2];
            unsigned long long a3 = As2[k * 65 + tr + 3];
            acc[0][0] = fma2(a0, wab, acc[0][0]); acc[0][1] = fma2(a0, wcd, acc[0][1]);
            acc[1][0] = fma2(a1, wab, acc[1][0]); acc[1][1] = fma2(a1, wcd, acc[1][1]);
            acc[2][0] = fma2(a2, wab, acc[2][0]); acc[2][1] = fma2(a2, wcd, acc[2][1]);
            acc[3][0] = fma2(a3, wab, acc[3][0]); acc[3][1] = fma2(a3, wcd, acc[3][1]);
        }
        __syncthreads();
    }
#pragma unroll
    for (int i = 0; i < 4; i++) {
        float c0, c1, c2, c3;
        unpack2(acc[i][0], c0, c1);
        unpack2(acc[i][1], c2, c3);
        *(float4*)&jb.C[(long long)(row0 + tr + i) * 64 + tc] =
            make_float4(c0, c1, c2, c3);
    }
}

// ---------------------------------------------------------------------------
// Logit GEMM body: 64 rows x 16 cols from raw activations via Wcat [K][16].
// smem = 64*130*4 + 128*16*4 = 41.5 KB.
// ---------------------------------------------------------------------------
__device__ __forceinline__ void logit_body(const GJob jb, int K, int kshift,
                                           int tile, int tid, char* sm) {
    float* As = (float*)sm;                   // [64][130]
    float* Wc = (float*)(sm + 64 * 130 * 4);  // [K][16]
    int row0 = tile * 64;
    for (int idx = tid; idx < 64 * K; idx += 256) {
        int r = idx >> kshift, k = idx & (K - 1);
        As[r * 130 + k] = a_prep(jb, (long long)(row0 + r) * K + k, k);
    }
    for (int idx = tid; idx < K * 16; idx += 256) Wc[idx] = jb.W[idx];
    __syncthreads();
    int c = tid & 15, rg = tid >> 4;          // 16 row-groups of 4
    float s0 = 0.f, s1 = 0.f, s2 = 0.f, s3 = 0.f;
    const float* r0 = As + (rg * 4 + 0) * 130;
    const float* r1 = As + (rg * 4 + 1) * 130;
    const float* r2 = As + (rg * 4 + 2) * 130;
    const float* r3 = As + (rg * 4 + 3) * 130;
#pragma unroll 4
    for (int k = 0; k < K; k++) {
        float wv = Wc[k * 16 + c];
        s0 += r0[k] * wv; s1 += r1[k] * wv; s2 += r2[k] * wv; s3 += r3[k] * wv;
    }
    long long ob = (long long)(row0 + rg * 4) * 16 + c;
    jb.C[ob] = s0; jb.C[ob + 16] = s1; jb.C[ob + 32] = s2; jb.C[ob + 48] = s3;
}

// ---------------------------------------------------------------------------
// combined launches
// ---------------------------------------------------------------------------
struct FeatB { GJob j[3]; };
struct LogitB { GJob j[2]; };

__global__ __launch_bounds__(256) void l0_kernel(
    const int* __restrict__ d0, const int* __restrict__ d1, const int* __restrict__ d2,
    int* __restrict__ deg, FeatB fb, LogitB lb) {
    __shared__ __align__(16) char sm[41600];
    int b = blockIdx.x;
    if (b < 3072) {
        int t = b * 256 + threadIdx.x;
        int g = t >> 18;
        int e = t & (NEDGE - 1);
        const int* ds = (g == 0) ? d0 : (g == 1) ? d1 : d2;
        atomicAdd(&deg[g * NNODE + ds[e]], 1);
    } else if (b < 3072 + 768) {
        int bb = b - 3072;
        feat_body(fb.j[bb >> 8], IN_DIM, bb & 255, threadIdx.x, sm);
    } else {
        int bb = b - 3840;
        logit_body(lb.j[bb >> 8], IN_DIM, 7, bb & 255, threadIdx.x, sm);
    }
}

__global__ __launch_bounds__(256) void l1_kernel(FeatB fb, LogitB lb) {
    __shared__ __align__(16) char sm[41600];
    int b = blockIdx.x;
    if (b < 512) {
        feat_body(fb.j[b >> 8], HID, b & 255, threadIdx.x, sm);
    } else {
        int bb = b - 512;
        logit_body(lb.j[bb >> 8], HID, 6, bb & 255, threadIdx.x, sm);
    }
}

// ---------------------------------------------------------------------------
// Fused GAT (R2-proven, 1 warp/node), batched; el/er have strides now
// ---------------------------------------------------------------------------
struct GatJob {
    const int* rp; const int* csr;
    const float* el; int elS;
    const float* er; int erS;
    const float* fs;
    const float* ba; int relu;
    float* out;
};
struct GatB { GatJob j[3]; };

#define MERGE(m, s)                                                        \
    {                                                                      \
        float om = __shfl_xor_sync(0xFFFFFFFFu, (m), off);                 \
        float os = __shfl_xor_sync(0xFFFFFFFFu, (s), off);                 \
        float nm = fmaxf((m), om);                                         \
        (s) = (s) * __expf((m) - nm) + os * __expf(om - nm);               \
        (m) = nm;                                                          \
    }

__global__ __launch_bounds__(256) void gat_kernel(GatB p) {
    GatJob jb = p.j[blockIdx.y];
    int w = (blockIdx.x * blockDim.x + threadIdx.x) >> 5;
    int lane = threadIdx.x & 31;
    if (w >= NNODE) return;
    int d = w;
    int beg = jb.rp[d], end = jb.rp[d + 1];
    float4 er4 = *(const float4*)(jb.er + (long long)d * jb.erS);

    float m0 = -1e30f, m1 = -1e30f, m2 = -1e30f, m3 = -1e30f;
    float s0 = 0.f, s1 = 0.f, s2 = 0.f, s3 = 0.f;
    for (int i = beg + lane; i < end; i += 32) {
        int s = jb.csr[i];
        float4 l4 = *(const float4*)(jb.el + (long long)s * jb.elS);
        float e0 = leaky(l4.x + er4.x);
        float e1 = leaky(l4.y + er4.y);
        float e2 = leaky(l4.z + er4.z);
        float e3 = leaky(l4.w + er4.w);
        float nm;
        nm = fmaxf(m0, e0); s0 = s0 * __expf(m0 - nm) + __expf(e0 - nm); m0 = nm;
        nm = fmaxf(m1, e1); s1 = s1 * __expf(m1 - nm) + __expf(e1 - nm); m1 = nm;
        nm = fmaxf(m2, e2); s2 = s2 * __expf(m2 - nm) + __expf(e2 - nm); m2 = nm;
        nm = fmaxf(m3, e3); s3 = s3 * __expf(m3 - nm) + __expf(e3 - nm); m3 = nm;
    }
#pragma unroll
    for (int off = 16; off; off >>= 1) {
        MERGE(m0, s0) MERGE(m1, s1) MERGE(m2, s2) MERGE(m3, s3)
    }
    float inv0 = 1.f / fmaxf(s0, 1e-9f);
    float inv1 = 1.f / fmaxf(s1, 1e-9f);
    float inv2 = 1.f / fmaxf(s2, 1e-9f);
    float inv3 = 1.f / fmaxf(s3, 1e-9f);

    bool hi = (lane & 16) != 0;
    float mA = hi ? m1 : m0, iA = hi ? inv1 : inv0, eA = hi ? er4.y : er4.x;
    float mB = hi ? m3 : m2, iB = hi ? inv3 : inv2, eB = hi ? er4.w : er4.z;
    float acc0 = 0.f, acc1 = 0.f;
    for (int i = beg; i < end; i++) {
        int s = jb.csr[i];
        float4 l4 = *(const float4*)(jb.el + (long long)s * jb.elS);
        float lA = hi ? l4.y : l4.x;
        float lB = hi ? l4.w : l4.z;
        float w0 = __expf(leaky(lA + eA) - mA) * iA;
        float w1 = __expf(leaky(lB + eB) - mB) * iB;
        const float* fr = jb.fs + (long long)s * HID;
        acc0 += fr[lane] * w0;
        acc1 += fr[lane + 32] * w1;
    }
    long long ob = (long long)d * HID;
    if (jb.ba) { acc0 += jb.ba[lane]; acc1 += jb.ba[lane + 32]; }
    if (jb.relu) { acc0 = fmaxf(acc0, 0.f); acc1 = fmaxf(acc1, 0.f); }
    jb.out[ob + lane] = acc0;
    jb.out[ob + lane + 32] = acc1;
}

// ---------------------------------------------------------------------------
// hf: sums layer-1 partials + biases + inline scalar C; l2-normalized concat
// ---------------------------------------------------------------------------
__global__ __launch_bounds__(256) void hf_kernel(
    const float* __restrict__ accW, const float* __restrict__ accC,
    const float* __restrict__ b1,
    const float* __restrict__ ln1_gb, const float* __restrict__ attn_w,
    const float* __restrict__ attn_b, const float* __restrict__ ln2_gb,
    const float* __restrict__ ffn_w1, const float* __restrict__ ffn_b1,
    const float* __restrict__ ffn_w2, const float* __restrict__ ffn_b2,
    float* __restrict__ hf) {
    __shared__ float sC;
    if (threadIdx.x == 0) {
        float y1 = ln1_gb[1];
        float v = y1 * attn_w[2] + attn_b[2];
        float o = v * attn_w[3] + attn_b[3];
        float y2 = ln2_gb[1];
        float f = ffn_b2[0];
        for (int j = 0; j < 16; j++) {
            float z = y2 * ffn_w1[j] + ffn_b1[j];
            float g = 0.5f * z * (1.0f + erff(z * 0.70710678118654752f));
            f += g * ffn_w2[j];
        }
        sC = o + f;
    }
    __syncthreads();
    float C = sC;

    int g = blockIdx.x * blockDim.x + threadIdx.x;
    int row = g >> 5;
    int lane = g & 31;
    if (row >= NNODE) return;
    long long base = (long long)row * HID;
    float v0 = accW[base + lane]      + accC[base + lane]
             + b1[lane]      + b1[64 + lane];
    float v1 = accW[base + lane + 32] + accC[base + lane + 32]
             + b1[lane + 32] + b1[96 + lane];
    float w0 = v0 + C, w1 = v1 + C;
    float s1 = v0 * v0 + v1 * v1;
    float s2 = w0 * w0 + w1 * w1;
#pragma unroll
    for (int o = 16; o; o >>= 1) {
        s1 += __shfl_xor_sync(0xFFFFFFFFu, s1, o);
        s2 += __shfl_xor_sync(0xFFFFFFFFu, s2, o);
    }
    float i1 = 1.f / fmaxf(sqrtf(s1), 1e-12f);
    float i2 = 1.f / fmaxf(sqrtf(s2), 1e-12f);
    long long hb = (long long)row * 128;
    hf[hb + lane]       = v0 * i1;
    hf[hb + lane + 32]  = v1 * i1;
    hf[hb + 64 + lane]  = w0 * i2;
    hf[hb + 96 + lane]  = w1 * i2;
}

// ---------------------------------------------------------------------------
// Final projection GEMM: 64x64 tile, FFMA2 inner loop, bias + Ncols guard
// ---------------------------------------------------------------------------
__global__ __launch_bounds__(256) void gemm_final_kernel(
    const float* __restrict__ A, const float* __restrict__ W,
    const float* __restrict__ bias, float* __restrict__ C,
    int K, int Ncols) {
    __shared__ __align__(16) char sm[32 * 65 * 8 + 32 * 64 * 4];
    unsigned long long* As2 = (unsigned long long*)sm;
    float* Ws = (float*)(sm + 32 * 65 * 8);
    int tid = threadIdx.x;
    int row0 = blockIdx.x * 64;
    int col0 = blockIdx.y * 64;
    int tr = (tid >> 4) * 4;
    int tc = (tid & 15) * 4;
    unsigned long long acc[4][2] = {};
    for (int kt = 0; kt < K; kt += 32) {
#pragma unroll
        for (int i = 0; i < 8; i++) {
            int idx = tid + i * 256;
            int r = idx >> 5, k = idx & 31;
            As2[k * 65 + r] = dup2(A[(long long)(row0 + r) * K + kt + k]);
        }
#pragma unroll
        for (int i = 0; i < 8; i++) {
            int idx = tid + i * 256;
            int k = idx >> 6, c = idx & 63;
            int gc = col0 + c;
            Ws[k * 64 + c] = (gc < Ncols) ? W[(long long)(kt + k) * Ncols + gc] : 0.0f;
        }
        __syncthreads();
#pragma unroll
        for (int k = 0; k < 32; k++) {
            float4 w = *(const float4*)&Ws[k * 64 + tc];
            unsigned long long wab = pack2(w.x, w.y);
            unsigned long long wcd = pack2(w.z, w.w);
            unsigned long long a0 = As2[k * 65 + tr];
            unsigned long long a1 = As2[k * 65 + tr + 1];
            unsigned long long a2 = As2[k * 65 + tr + 2];
            unsigned long long a3 = As2[k * 65 + tr + 3];
            acc[0][0] = fma2(a0, wab, acc[0][0]); acc[0][1] = fma2(a0, wcd, acc[0][1]);
            acc[1][0] = fma2(a1, wab, acc[1][0]); acc[1][1] = fma2(a1, wcd, acc[1][1]);
            acc[2][0] = fma2(a2, wab, acc[2][0]); acc[2][1] = fma2(a2, wcd, acc[2][1]);
            acc[3][0] = fma2(a3, wab, acc[3][0]); acc[3][1] = fma2(a3, wcd, acc[3][1]);
        }
        __syncthreads();
    }
#pragma unroll
    for (int i = 0; i < 4; i++) {
        long long r = row0 + tr + i;
        float c0, c1, c2, c3;
        unpack2(acc[i][0], c0, c1);
        unpack2(acc[i][1], c2, c3);
        int c = col0 + tc;
        if (c + 0 < Ncols) C[r * Ncols + c + 0] = c0 + bias[c + 0];
        if (c + 1 < Ncols) C[r * Ncols + c + 1] = c1 + bias[c + 1];
        if (c + 2 < Ncols) C[r * Ncols + c + 2] = c2 + bias[c + 2];
        if (c + 3 < Ncols) C[r * Ncols + c + 3] = c3 + bias[c + 3];
    }
}

// ---------------------------------------------------------------------------
extern "C" void kernel_launch(void* const* d_in, const int* in_sizes, int n_in,
                              void* d_out, int out_size) {
    const float* x_author = (const float*)d_in[0];
    const float* x_paper  = (const float*)d_in[1];
    const float* ntype    = (const float*)d_in[2];
    const float* W0       = (const float*)d_in[3];
    const float* al0      = (const float*)d_in[4];
    const float* ar0      = (const float*)d_in[5];
    const float* b0       = (const float*)d_in[6];
    const float* W1       = (const float*)d_in[7];
    const float* al1      = (const float*)d_in[8];
    const float* ar1      = (const float*)d_in[9];
    const float* b1       = (const float*)d_in[10];
    const float* ln1_gb   = (const float*)d_in[11];
    const float* attn_w   = (const float*)d_in[12];
    const float* attn_b   = (const float*)d_in[13];
    const float* ln2_gb   = (const float*)d_in[14];
    const float* ffn_w1   = (const float*)d_in[15];
    const float* ffn_b1   = (const float*)d_in[16];
    const float* ffn_w2   = (const float*)d_in[17];
    const float* ffn_b2   = (const float*)d_in[18];
    const float* lin_W    = (const float*)d_in[19];
    const float* lin_b    = (const float*)d_in[20];
    const int* src_w = (const int*)d_in[21];
    const int* dst_w = (const int*)d_in[22];
    const int* src_c = (const int*)d_in[23];
    const int* dst_c = (const int*)d_in[24];
    const int* src_r = (const int*)d_in[25];
    const int* dst_r = (const int*)d_in[26];
    float* out = (float*)d_out;

    float* S = nullptr;
    cudaGetSymbolAddress((void**)&S, g_scratch);

    float* Fa0   = S + OFF_FA0;
    float* Fp1   = S + OFF_FP1;
    float* Fp2   = S + OFF_FP2;
    float* F1a   = S + OFF_F1A;
    float* F1pc  = S + OFF_F1PC;
    float* outpW = S + OFF_OUTPW;
    float* outpC = S + OFF_OUTPC;
    float* o1w   = S + OFF_O1W;
    float* o1c   = S + OFF_O1C;
    float* ha1   = S + OFF_HA1;
    float* hf    = S + OFF_HF;
    float* LA    = S + OFF_LA;
    float* LP    = S + OFF_LP;
    float* L1A   = S + OFF_L1A;
    float* L1P   = S + OFF_L1P;
    float* wal   = S + OFF_WAL;
    int* degB = (int*)(S + OFF_DEG);
    int* rpB  = (int*)(S + OFF_RP);
    int* csrB = (int*)(S + OFF_CSR);

    const int* rp_w = rpB + 0 * (NNODE + 1);
    const int* rp_c = rpB + 1 * (NNODE + 1);
    const int* rp_r = rpB + 2 * (NNODE + 1);
    const int* csr_w = csrB + 0LL * NEDGE;
    const int* csr_c = csrB + 1LL * NEDGE;
    const int* csr_r = csrB + 2LL * NEDGE;

    const float* nt0 = ntype;
    const float* nt1 = ntype + IN_DIM;

    // L1: zero deg + Wal precompute
    misc_kernel<<<192 + 24, 256>>>(degB, W0, W1, al0, ar0, al1, ar1, ntype, wal);

    // L2: hist + 3 feature GEMMs + 2 logit GEMMs (layer 0), co-launched
    FeatB f0;
    f0.j[0] = { x_author, nullptr, nt0, nullptr, nullptr, 0, W0 + 0 * 8192, Fa0 };
    f0.j[1] = { x_paper,  nullptr, nt1, nullptr, nullptr, 0, W0 + 1 * 8192, Fp1 };
    f0.j[2] = { x_paper,  nullptr, nt1, nullptr, nullptr, 0, W0 + 2 * 8192, Fp2 };
    LogitB lg0;
    lg0.j[0] = { x_author, nullptr, nullptr, nullptr, nullptr, 0, wal + 0,    LA };
    lg0.j[1] = { x_paper,  nullptr, nullptr, nullptr, nullptr, 0, wal + 2048, LP };
    l0_kernel<<<3072 + 768 + 512, 256>>>(dst_w, dst_c, dst_r, degB, f0, lg0);

    // L3: scan (row_ptr + cursors)
    scan3_kernel<<<3, 1024>>>(degB, rpB);

    // L4: scatter (CSR fill)
    scatter_kernel<<<3072, 256>>>(src_w, dst_w, src_c, dst_c, src_r, dst_r,
                                  degB, csrB);

    // L5: three layer-0 GATs batched
    //   LA cols: [el_w 0-3 | er_r 4-7];  LP cols: [er_w 0-3 | el_c 4-7 | er_c 8-11 | el_r 12-15]
    GatB ga;
    ga.j[0] = { rp_w, csr_w, LA + 0, 16, LP + 0,  16, Fa0, nullptr,  0, outpW };
    ga.j[1] = { rp_c, csr_c, LP + 4, 16, LP + 8,  16, Fp1, nullptr,  0, outpC };
    ga.j[2] = { rp_r, csr_r, LP + 12, 16, LA + 4, 16, Fp2, b0 + 128, 1, ha1 };
    gat_kernel<<<dim3(2048, 3), 256>>>(ga);

    // L6: layer-1 feature + logit GEMMs (hp1 prep fused into A-load)
    FeatB f1;
    f1.j[0] = { ha1,   nullptr, nullptr, nullptr, nullptr, 0, W1 + 0 * 4096, F1a };
    f1.j[1] = { outpW, outpC,   nullptr, b0,      b0 + 64, 1, W1 + 1 * 4096, F1pc };
    f1.j[2] = { nullptr, nullptr, nullptr, nullptr, nullptr, 0, nullptr, nullptr };
    LogitB lg1;
    lg1.j[0] = { ha1,   nullptr, nullptr, nullptr, nullptr, 0, wal + 4096, L1A };
    lg1.j[1] = { outpW, outpC,   nullptr, b0,      b0 + 64, 1, wal + 5120, L1P };
    l1_kernel<<<512 + 512, 256>>>(f1, lg1);

    // L7: two layer-1 GATs batched
    //   L1A cols: [el1w 0-3];  L1P cols: [er1w 0-3 | el1c 4-7 | er1c 8-11]
    GatB gc;
    gc.j[0] = { rp_w, csr_w, L1A + 0, 16, L1P + 0, 16, F1a,  nullptr, 0, o1w };
    gc.j[1] = { rp_c, csr_c, L1P + 4, 16, L1P + 8, 16, F1pc, nullptr, 0, o1c };
    gc.j[2] = { nullptr, nullptr, nullptr, 0, nullptr, 0, nullptr, nullptr, 0, nullptr };
    gat_kernel<<<dim3(2048, 2), 256>>>(gc);

    // L8: hf (partial sum + inline C + l2-normalized concat)
    hf_kernel<<<2048, 256>>>(o1w, o1c, b1, ln1_gb, attn_w, attn_b, ln2_gb,
                             ffn_w1, ffn_b1, ffn_w2, ffn_b2, hf);

    // L9: final projection (FFMA2)
    gemm_final_kernel<<<dim3(256, 6), 256>>>(hf, lin_W, lin_b, out, 2 * HID, OUTF);
}